// round 3
// baseline (speedup 1.0000x reference)
#include <cuda_runtime.h>
#include <stdint.h>

#define BB 4
#define AA 3
#define HH 168
#define WW 256
#define NN (HH*WW*AA)     // 129024
#define MM 32
#define NBINS 4096
#define CAPB 128
#define NPI 256
#define NPOSMAX 128
#define FG 0.7f
#define BG 0.3f
#define BETA (1.0f/9.0f)

// ---------------- scratch (device globals; zeroed by k_init each launch) ----
__device__ unsigned            d_colmax[BB*MM];
__device__ uint2               d_imgkey[BB];
__device__ int                 d_pcnt[BB*NBINS];
__device__ int                 d_ncnt[BB*NBINS];
__device__ float               d_psc [BB*NBINS];
__device__ float               d_psr [BB*NBINS];
__device__ float               d_nsc [BB*NBINS];
__device__ unsigned long long  d_pkey[(size_t)BB*NBINS*CAPB];
__device__ unsigned long long  d_nkey[(size_t)BB*NBINS*CAPB];
__device__ float               d_pvc [(size_t)BB*NBINS*CAPB];
__device__ float               d_pvr [(size_t)BB*NBINS*CAPB];
__device__ float               d_nvc [(size_t)BB*NBINS*CAPB];
__device__ float               d_icls[BB];
__device__ float               d_ireg[BB];
__device__ int                 d_icnt[BB];

// ---------------- threefry2x32 (exact JAX rotation/injection schedule) ------
__device__ __forceinline__ void tf2x32(unsigned k0, unsigned k1,
                                       unsigned x0, unsigned x1,
                                       unsigned &o0, unsigned &o1) {
    unsigned k2 = k0 ^ k1 ^ 0x1BD11BDAu;
    x0 += k0; x1 += k1;
#define TF_RND(r) { x0 += x1; x1 = (x1<<(r))|(x1>>(32-(r))); x1 ^= x0; }
    TF_RND(13) TF_RND(15) TF_RND(26) TF_RND(6)   x0 += k1; x1 += k2 + 1u;
    TF_RND(17) TF_RND(29) TF_RND(16) TF_RND(24)  x0 += k2; x1 += k0 + 2u;
    TF_RND(13) TF_RND(15) TF_RND(26) TF_RND(6)   x0 += k0; x1 += k1 + 3u;
    TF_RND(17) TF_RND(29) TF_RND(16) TF_RND(24)  x0 += k1; x1 += k2 + 4u;
    TF_RND(13) TF_RND(15) TF_RND(26) TF_RND(6)   x0 += k2; x1 += k0 + 5u;
#undef TF_RND
    o0 = x0; o1 = x1;
}

// ---------------- IoU with strict round-to-nearest (no contraction) ---------
__device__ __forceinline__ float barea(float x1, float y1, float x2, float y2) {
    return __fmul_rn(__fadd_rn(__fsub_rn(x2, x1), 1.0f),
                     __fadd_rn(__fsub_rn(y2, y1), 1.0f));
}

__device__ __forceinline__ float iouv(float ax1, float ay1, float ax2, float ay2, float aar,
                                      float tx1, float ty1, float tx2, float ty2, float tar) {
    float xtl = fmaxf(ax1, tx1), ytl = fmaxf(ay1, ty1);
    float xrb = fminf(ax2, tx2), yrb = fminf(ay2, ty2);
    float iw = fmaxf(__fadd_rn(__fsub_rn(xrb, xtl), 1.0f), 0.0f);
    float ih = fmaxf(__fadd_rn(__fsub_rn(yrb, ytl), 1.0f), 0.0f);
    float inter = __fmul_rn(iw, ih);
    float uni = __fsub_rn(__fadd_rn(aar, tar), inter);
    return __fdiv_rn(inter, uni);
}

// ---------------- kernel 0: zero scratch + compute image keys ---------------
__global__ void k_init() {
    int idx = blockIdx.x * blockDim.x + threadIdx.x;
    if (idx < BB*NBINS) {
        d_pcnt[idx] = 0; d_ncnt[idx] = 0;
        d_psc[idx] = 0.f; d_psr[idx] = 0.f; d_nsc[idx] = 0.f;
    }
    if (idx < BB*MM) d_colmax[idx] = 0u;
    if (idx < BB) {
        // fold-like split (threefry_partitionable=True): key_b = threefry((0,42),(0,b))
        unsigned o0, o1;
        tf2x32(0u, 42u, 0u, (unsigned)idx, o0, o1);
        d_imgkey[idx] = make_uint2(o0, o1);
    }
}

// ---------------- kernel 1: per-target column max of IoU --------------------
__global__ void k_colmax(const float* __restrict__ anchors,
                         const float* __restrict__ targets) {
    const int BLK = NN / 256;
    int b = blockIdx.x / BLK;
    int i = (blockIdx.x % BLK) * 256 + threadIdx.x;

    __shared__ float tx1[MM], ty1[MM], tx2[MM], ty2[MM], tar[MM];
    __shared__ unsigned smax[MM];
    if (threadIdx.x < MM) {
        const float* t = targets + ((size_t)b*MM + threadIdx.x)*4;
        float a = t[0], c = t[1], d = t[2], e = t[3];
        tx1[threadIdx.x]=a; ty1[threadIdx.x]=c; tx2[threadIdx.x]=d; ty2[threadIdx.x]=e;
        tar[threadIdx.x] = barea(a, c, d, e);
        smax[threadIdx.x] = 0u;
    }
    __syncthreads();

    float4 A = reinterpret_cast<const float4*>(anchors)[(size_t)b*NN + i];
    float aar = barea(A.x, A.y, A.z, A.w);

    for (int j = 0; j < MM; j++) {
        float v = iouv(A.x, A.y, A.z, A.w, aar, tx1[j], ty1[j], tx2[j], ty2[j], tar[j]);
        #pragma unroll
        for (int off = 16; off; off >>= 1)
            v = fmaxf(v, __shfl_xor_sync(0xFFFFFFFFu, v, off));
        if ((threadIdx.x & 31) == 0)
            atomicMax(&smax[j], __float_as_uint(v));
    }
    __syncthreads();
    if (threadIdx.x < MM)
        atomicMax(&d_colmax[b*MM + threadIdx.x], smax[threadIdx.x]);
}

// ---------------- kernel 2: classify anchors, emit loss terms into bins -----
__global__ void k_classify(const float* __restrict__ anchors,
                           const float* __restrict__ logits,
                           const float* __restrict__ bregs,
                           const float* __restrict__ sizes,
                           const float* __restrict__ targets) {
    const int BLK = NN / 256;
    int b = blockIdx.x / BLK;
    int i = (blockIdx.x % BLK) * 256 + threadIdx.x;

    __shared__ float tx1[MM], ty1[MM], tx2[MM], ty2[MM], tar[MM];
    __shared__ unsigned scol[MM];
    __shared__ float ssize[2];
    if (threadIdx.x < MM) {
        const float* t = targets + ((size_t)b*MM + threadIdx.x)*4;
        float a = t[0], c = t[1], d = t[2], e = t[3];
        tx1[threadIdx.x]=a; ty1[threadIdx.x]=c; tx2[threadIdx.x]=d; ty2[threadIdx.x]=e;
        tar[threadIdx.x] = barea(a, c, d, e);
        scol[threadIdx.x] = d_colmax[b*MM + threadIdx.x];
    }
    if (threadIdx.x < 2) ssize[threadIdx.x] = sizes[b*2 + threadIdx.x];
    __syncthreads();

    float4 A = reinterpret_cast<const float4*>(anchors)[(size_t)b*NN + i];
    float aar = barea(A.x, A.y, A.z, A.w);

    float best = -1.0f; int ori = 0; bool restore = false;
    for (int j = 0; j < MM; j++) {
        float v = iouv(A.x, A.y, A.z, A.w, aar, tx1[j], ty1[j], tx2[j], ty2[j], tar[j]);
        restore = restore || (__float_as_uint(v) == scol[j]);
        if (v > best) { best = v; ori = j; }
    }
    bool inside = (A.x >= 0.f) && (A.y >= 0.f) &&
                  (A.z <= ssize[1] - 1.0f) && (A.w <= ssize[0] - 1.0f);
    bool pos = inside && (best >= FG || restore);
    bool neg = inside && !restore && (best < BG);
    if (!pos && !neg) return;

    // exact JAX uniform priority: bits = o0^o1 of threefry(key_b, (0, i)); r = (bits>>9)*2^-23
    uint2 kb = d_imgkey[b];
    unsigned o0, o1;
    tf2x32(kb.x, kb.y, 0u, (unsigned)i, o0, o1);
    unsigned prio = (o0 ^ o1) >> 9;
    unsigned long long kk = ((unsigned long long)prio << 32) | (0xFFFFFFFFu - (unsigned)i);
    int bin = (int)(prio >> 11);

    int ai = i % AA; int hw = i / AA; int wx = hw % WW; int hy = hw / WW;
    float l = logits[(((size_t)b*AA + ai)*HH + hy)*WW + wx];
    float sp = log1pf(expf(-fabsf(l)));
    float cls = fmaxf(l, 0.f) + sp;          // BCE(l, 0)

    if (pos) {
        cls -= l;                            // BCE(l, 1) = max(l,0) - l + softplus
        float ws = A.z - A.x + 1.0f, hs = A.w - A.y + 1.0f;
        float xc = A.x + 0.5f*ws,   yc = A.y + 0.5f*hs;
        float tws = tx2[ori]-tx1[ori]+1.0f, ths = ty2[ori]-ty1[ori]+1.0f;
        float txc = tx1[ori]+0.5f*tws,      tyc = ty1[ori]+0.5f*ths;
        float off[4] = { (txc - xc)/ws, (tyc - yc)/hs, logf(tws/ws), logf(ths/hs) };
        float reg = 0.f;
        #pragma unroll
        for (int c = 0; c < 4; c++) {
            float br = bregs[(((size_t)b*4*AA + ai*4 + c)*HH + hy)*WW + wx];
            float d = fabsf(br - off[c]);
            reg += (d < BETA) ? 0.5f*d*d/BETA : d - 0.5f*BETA;
        }
        int idx = b*NBINS + bin;
        int c0 = atomicAdd(&d_pcnt[idx], 1);
        atomicAdd(&d_psc[idx], cls);
        atomicAdd(&d_psr[idx], reg);
        if (c0 < CAPB) {
            size_t e = (size_t)idx*CAPB + c0;
            d_pkey[e] = kk; d_pvc[e] = cls; d_pvr[e] = reg;
        }
    } else {
        int idx = b*NBINS + bin;
        int c0 = atomicAdd(&d_ncnt[idx], 1);
        atomicAdd(&d_nsc[idx], cls);
        if (c0 < CAPB) {
            size_t e = (size_t)idx*CAPB + c0;
            d_nkey[e] = kk; d_nvc[e] = cls;
        }
    }
}

// ---------------- kernel 3: exact top-K selection per image -----------------
__device__ int sel_phase(int b, int K,
                         const int* __restrict__ cntg,
                         const float* __restrict__ s1g, const float* __restrict__ s2g,
                         const unsigned long long* __restrict__ keyg,
                         const float* __restrict__ v1g, const float* __restrict__ v2g,
                         bool has2,
                         int* schunk, float* sf1, float* sf2,
                         unsigned long long* skey, float* sv1, float* sv2,
                         int* sint, float& out1, float& out2) {
    int t = threadIdx.x;
    const int* c = cntg + b*NBINS;
    int hi0 = NBINS - 1 - t*16;                 // thread t owns 16 bins, descending

    int cs = 0;
    #pragma unroll
    for (int k = 0; k < 16; k++) cs += c[hi0 - k];
    schunk[t] = cs;
    __syncthreads();

    // inclusive scan (descending-bin order) over 256 chunk sums
    int incl = cs;
    for (int off = 1; off < 256; off <<= 1) {
        int add = (t >= off) ? schunk[t - off] : 0;
        __syncthreads();
        incl += add;
        schunk[t] = incl;
        __syncthreads();
    }
    int excl = incl - cs;
    if (t == 255) sint[0] = incl;
    __syncthreads();
    int total = sint[0];

    if (total > K) {
        if (excl < K && incl >= K) {            // exactly one thread
            int cum = excl;
            for (int k = 0; k < 16; k++) {
                int bi = hi0 - k; int cc = c[bi];
                if (cum + cc >= K) { sint[1] = bi; sint[2] = K - cum; break; }
                cum += cc;
            }
        }
    } else if (t == 0) { sint[1] = -1; sint[2] = 0; }
    __syncthreads();
    int binT = sint[1], Kp = sint[2];

    float a1 = 0.f, a2 = 0.f;
    for (int k = 0; k < 16; k++) {
        int bi = hi0 - k;
        if (bi > binT) {
            a1 += s1g[b*NBINS + bi];
            if (has2) a2 += s2g[b*NBINS + bi];
        }
    }
    if (binT >= 0) {
        int nt = c[binT]; if (nt > CAPB) nt = CAPB;
        size_t base = ((size_t)b*NBINS + binT)*CAPB;
        for (int e = t; e < nt; e += 256) {
            skey[e] = keyg[base + e];
            sv1[e]  = v1g[base + e];
            if (has2) sv2[e] = v2g[base + e];
        }
        __syncthreads();
        for (int e = t; e < nt; e += 256) {
            unsigned long long ke = skey[e];
            int rank = 0;
            for (int q = 0; q < nt; q++) rank += (skey[q] > ke);
            if (rank < Kp) { a1 += sv1[e]; if (has2) a2 += sv2[e]; }
        }
    }
    __syncthreads();
    sf1[t] = a1; sf2[t] = a2;
    __syncthreads();
    for (int off = 128; off; off >>= 1) {
        if (t < off) { sf1[t] += sf1[t + off]; sf2[t] += sf2[t + off]; }
        __syncthreads();
    }
    out1 = sf1[0]; out2 = sf2[0];
    int sel = (total < K) ? total : K;
    __syncthreads();
    return sel;
}

__global__ void k_select() {
    __shared__ int schunk[256];
    __shared__ float sf1[256], sf2[256];
    __shared__ unsigned long long skey[CAPB];
    __shared__ float sv1[CAPB], sv2[CAPB];
    __shared__ int sint[4];
    int b = blockIdx.x;

    float pc, pr;
    int np = sel_phase(b, NPOSMAX, d_pcnt, d_psc, d_psr, d_pkey, d_pvc, d_pvr, true,
                       schunk, sf1, sf2, skey, sv1, sv2, sint, pc, pr);
    float nc, nd;
    int nn = sel_phase(b, NPI - np, d_ncnt, d_nsc, d_nsc, d_nkey, d_nvc, d_nvc, false,
                       schunk, sf1, sf2, skey, sv1, sv2, sint, nc, nd);
    if (threadIdx.x == 0) {
        d_icls[b] = pc + nc;
        d_ireg[b] = pr;
        d_icnt[b] = np + nn;
    }
}

// ---------------- kernel 4: combine and normalize ---------------------------
__global__ void k_final(float* __restrict__ out) {
    float cs = 0.f, rs = 0.f; int cn = 0;
    for (int b = 0; b < BB; b++) { cs += d_icls[b]; rs += d_ireg[b]; cn += d_icnt[b]; }
    float tot = (float)cn;
    out[0] = cs / tot;
    out[1] = rs / tot;
}

// ---------------- launch ----------------------------------------------------
extern "C" void kernel_launch(void* const* d_in, const int* in_sizes, int n_in,
                              void* d_out, int out_size) {
    const float* anchors = (const float*)d_in[0];
    const float* logits  = (const float*)d_in[1];
    const float* bregs   = (const float*)d_in[2];
    const float* sizes   = (const float*)d_in[3];
    const float* targets = (const float*)d_in[4];
    float* out = (float*)d_out;

    k_init<<<(BB*NBINS + 255)/256, 256>>>();
    k_colmax<<<BB*(NN/256), 256>>>(anchors, targets);
    k_classify<<<BB*(NN/256), 256>>>(anchors, logits, bregs, sizes, targets);
    k_select<<<BB, 256>>>();
    k_final<<<1, 1>>>(out);
}

// round 5
// speedup vs baseline: 1.5626x; 1.5626x over previous
#include <cuda_runtime.h>
#include <stdint.h>

#define BB 4
#define AA 3
#define HH 168
#define WW 256
#define NN (HH*WW*AA)     // 129024
#define MM 32
#define NBINS 4096
#define CAPB 128
#define NPI 256
#define NPOSMAX 128
#define FG 0.7f
#define BG 0.3f
#define BETA (1.0f/9.0f)

// ---------------- scratch (device globals; zeroed by k_init each launch) ----
__device__ unsigned            d_colmax[BB*MM];
__device__ uint2               d_imgkey[BB];
__device__ int                 d_pcnt[BB*NBINS];
__device__ int                 d_ncnt[BB*NBINS];
__device__ float               d_psc [BB*NBINS];
__device__ float               d_psr [BB*NBINS];
__device__ float               d_nsc [BB*NBINS];
__device__ unsigned long long  d_pkey[(size_t)BB*NBINS*CAPB];
__device__ unsigned long long  d_nkey[(size_t)BB*NBINS*CAPB];
__device__ float               d_pvc [(size_t)BB*NBINS*CAPB];
__device__ float               d_pvr [(size_t)BB*NBINS*CAPB];
__device__ float               d_nvc [(size_t)BB*NBINS*CAPB];
__device__ float               d_ocls[2*BB];
__device__ float               d_oreg[2*BB];
__device__ int                 d_ocnt[2*BB];

// ---------------- threefry2x32 (exact JAX rotation/injection schedule) ------
__device__ __forceinline__ void tf2x32(unsigned k0, unsigned k1,
                                       unsigned x0, unsigned x1,
                                       unsigned &o0, unsigned &o1) {
    unsigned k2 = k0 ^ k1 ^ 0x1BD11BDAu;
    x0 += k0; x1 += k1;
#define TF_RND(r) { x0 += x1; x1 = (x1<<(r))|(x1>>(32-(r))); x1 ^= x0; }
    TF_RND(13) TF_RND(15) TF_RND(26) TF_RND(6)   x0 += k1; x1 += k2 + 1u;
    TF_RND(17) TF_RND(29) TF_RND(16) TF_RND(24)  x0 += k2; x1 += k0 + 2u;
    TF_RND(13) TF_RND(15) TF_RND(26) TF_RND(6)   x0 += k0; x1 += k1 + 3u;
    TF_RND(17) TF_RND(29) TF_RND(16) TF_RND(24)  x0 += k1; x1 += k2 + 4u;
    TF_RND(13) TF_RND(15) TF_RND(26) TF_RND(6)   x0 += k2; x1 += k0 + 5u;
#undef TF_RND
    o0 = x0; o1 = x1;
}

// ---------------- IoU pieces, strict round-to-nearest (no contraction) ------
__device__ __forceinline__ float barea(float x1, float y1, float x2, float y2) {
    return __fmul_rn(__fadd_rn(__fsub_rn(x2, x1), 1.0f),
                     __fadd_rn(__fsub_rn(y2, y1), 1.0f));
}

__device__ __forceinline__ void iou_iu(float ax1, float ay1, float ax2, float ay2, float aar,
                                       float tx1, float ty1, float tx2, float ty2, float tar,
                                       float& inter, float& uni) {
    float xtl = fmaxf(ax1, tx1), ytl = fmaxf(ay1, ty1);
    float xrb = fminf(ax2, tx2), yrb = fminf(ay2, ty2);
    float iw = fmaxf(__fadd_rn(__fsub_rn(xrb, xtl), 1.0f), 0.0f);
    float ih = fmaxf(__fadd_rn(__fsub_rn(yrb, ytl), 1.0f), 0.0f);
    inter = __fmul_rn(iw, ih);
    uni   = __fsub_rn(__fadd_rn(aar, tar), inter);
}

// ---------------- kernel 0: zero scratch + compute image keys ---------------
__global__ void k_init() {
    int idx = blockIdx.x * blockDim.x + threadIdx.x;
    if (idx < BB*NBINS) {
        d_pcnt[idx] = 0; d_ncnt[idx] = 0;
        d_psc[idx] = 0.f; d_psr[idx] = 0.f; d_nsc[idx] = 0.f;
    }
    if (idx < BB*MM) d_colmax[idx] = 0u;
    if (idx < BB) {
        unsigned o0, o1;
        tf2x32(0u, 42u, 0u, (unsigned)idx, o0, o1);
        d_imgkey[idx] = make_uint2(o0, o1);
    }
}

// ---------------- kernel 1: per-target column max of IoU --------------------
// Approx prefilter (__fdividef, <=2ulp) + redux warp max; exact __fdiv_rn only
// for lanes within 2e-6 of warp max (true max lane always survives: combined
// approx+rounding error < 5e-7 << 2e-6).
__global__ void k_colmax(const float* __restrict__ anchors,
                         const float* __restrict__ targets) {
    const int BLK = NN / 256;
    int b = blockIdx.x / BLK;
    int i = (blockIdx.x % BLK) * 256 + threadIdx.x;

    __shared__ float tx1[MM], ty1[MM], tx2[MM], ty2[MM], tar[MM];
    __shared__ unsigned smax[MM];
    if (threadIdx.x < MM) {
        const float* t = targets + ((size_t)b*MM + threadIdx.x)*4;
        float a = t[0], c = t[1], d = t[2], e = t[3];
        tx1[threadIdx.x]=a; ty1[threadIdx.x]=c; tx2[threadIdx.x]=d; ty2[threadIdx.x]=e;
        tar[threadIdx.x] = barea(a, c, d, e);
        smax[threadIdx.x] = 0u;
    }
    __syncthreads();

    float4 A = reinterpret_cast<const float4*>(anchors)[(size_t)b*NN + i];
    float aar = barea(A.x, A.y, A.z, A.w);

    #pragma unroll 8
    for (int j = 0; j < MM; j++) {
        float inter, u;
        iou_iu(A.x, A.y, A.z, A.w, aar, tx1[j], ty1[j], tx2[j], ty2[j], tar[j], inter, u);
        float qa = (inter > 0.f) ? __fdividef(inter, u) : 0.f;
        unsigned wmb = __reduce_max_sync(0xFFFFFFFFu, __float_as_uint(qa));
        float wmf = __uint_as_float(wmb);
        if (inter > 0.f && qa >= __fmul_rn(wmf, 0.999998f)) {
            float q = __fdiv_rn(inter, u);
            atomicMax(&smax[j], __float_as_uint(q));
        }
    }
    __syncthreads();
    if (threadIdx.x < MM)
        atomicMax(&d_colmax[b*MM + threadIdx.x], smax[threadIdx.x]);
}

// ---------------- kernel 2: classify anchors, emit loss terms into bins -----
// Row argmax via exact EFT cross-product compare on (inter, union) pairs;
// single __fdiv_rn for the row max; restore checked via prefilter + rare div.
__global__ void k_classify(const float* __restrict__ anchors,
                           const float* __restrict__ logits,
                           const float* __restrict__ bregs,
                           const float* __restrict__ sizes,
                           const float* __restrict__ targets) {
    const int BLK = NN / 256;
    int b = blockIdx.x / BLK;
    int i = (blockIdx.x % BLK) * 256 + threadIdx.x;

    __shared__ float tx1[MM], ty1[MM], tx2[MM], ty2[MM], tar[MM], slo[MM];
    __shared__ unsigned scol[MM];
    __shared__ float ssize[2];
    if (threadIdx.x < MM) {
        const float* t = targets + ((size_t)b*MM + threadIdx.x)*4;
        float a = t[0], c = t[1], d = t[2], e = t[3];
        tx1[threadIdx.x]=a; ty1[threadIdx.x]=c; tx2[threadIdx.x]=d; ty2[threadIdx.x]=e;
        tar[threadIdx.x] = barea(a, c, d, e);
        unsigned cb = d_colmax[b*MM + threadIdx.x];
        scol[threadIdx.x] = cb;
        slo[threadIdx.x] = __fmul_rn(__uint_as_float(cb), 0.999998f);
    }
    if (threadIdx.x < 2) ssize[threadIdx.x] = sizes[b*2 + threadIdx.x];
    __syncthreads();

    float4 A = reinterpret_cast<const float4*>(anchors)[(size_t)b*NN + i];
    bool inside = (A.x >= 0.f) && (A.y >= 0.f) &&
                  (A.z <= ssize[1] - 1.0f) && (A.w <= ssize[0] - 1.0f);
    if (!inside) return;   // inds = -2 regardless of restore -> excluded

    float aar = barea(A.x, A.y, A.z, A.w);

    float bi = -1.0f, bu = 1.0f; int ori = 0; bool restore = false;
    #pragma unroll 8
    for (int j = 0; j < MM; j++) {
        float inter, u;
        iou_iu(A.x, A.y, A.z, A.w, aar, tx1[j], ty1[j], tx2[j], ty2[j], tar[j], inter, u);
        // exact compare inter/u > bi/bu via error-free 2-products
        float p1 = __fmul_rn(inter, bu), e1 = __fmaf_rn(inter, bu, -p1);
        float p2 = __fmul_rn(bi, u),     e2 = __fmaf_rn(bi, u, -p2);
        bool g = (p1 > p2) || (p1 == p2 && e1 > e2);
        if (g) { bi = inter; bu = u; ori = j; }
        // restore prefilter: only near-colmax pairs pay a division
        if (inter > 0.f && inter >= __fmul_rn(slo[j], u)) {
            float q = __fdiv_rn(inter, u);
            restore = restore || (__float_as_uint(q) == scol[j]);
        }
    }
    float best = __fdiv_rn(bi, bu);  // == max of rounded (round is monotone)

    bool pos = (best >= FG) || restore;
    bool neg = (!restore) && (best < BG);
    if (!pos && !neg) return;

    // exact JAX uniform priority: bits = o0^o1 of threefry(key_b, (0, i))
    uint2 kb = d_imgkey[b];
    unsigned o0, o1;
    tf2x32(kb.x, kb.y, 0u, (unsigned)i, o0, o1);
    unsigned prio = (o0 ^ o1) >> 9;
    unsigned long long kk = ((unsigned long long)prio << 32) | (0xFFFFFFFFu - (unsigned)i);
    int bin = (int)(prio >> 11);

    int ai = i % AA; int hw = i / AA; int wx = hw % WW; int hy = hw / WW;
    float l = logits[(((size_t)b*AA + ai)*HH + hy)*WW + wx];
    float sp = log1pf(expf(-fabsf(l)));
    float cls = fmaxf(l, 0.f) + sp;          // BCE(l, 0)

    if (pos) {
        cls -= l;                            // BCE(l, 1)
        float ws = A.z - A.x + 1.0f, hs = A.w - A.y + 1.0f;
        float xc = A.x + 0.5f*ws,   yc = A.y + 0.5f*hs;
        float tws = tx2[ori]-tx1[ori]+1.0f, ths = ty2[ori]-ty1[ori]+1.0f;
        float txc = tx1[ori]+0.5f*tws,      tyc = ty1[ori]+0.5f*ths;
        float off[4] = { (txc - xc)/ws, (tyc - yc)/hs, logf(tws/ws), logf(ths/hs) };
        float reg = 0.f;
        #pragma unroll
        for (int c = 0; c < 4; c++) {
            float br = bregs[(((size_t)b*4*AA + ai*4 + c)*HH + hy)*WW + wx];
            float d = fabsf(br - off[c]);
            reg += (d < BETA) ? 0.5f*d*d/BETA : d - 0.5f*BETA;
        }
        int idx = b*NBINS + bin;
        int c0 = atomicAdd(&d_pcnt[idx], 1);
        atomicAdd(&d_psc[idx], cls);
        atomicAdd(&d_psr[idx], reg);
        if (c0 < CAPB) {
            size_t e = (size_t)idx*CAPB + c0;
            d_pkey[e] = kk; d_pvc[e] = cls; d_pvr[e] = reg;
        }
    } else {
        int idx = b*NBINS + bin;
        int c0 = atomicAdd(&d_ncnt[idx], 1);
        atomicAdd(&d_nsc[idx], cls);
        if (c0 < CAPB) {
            size_t e = (size_t)idx*CAPB + c0;
            d_nkey[e] = kk; d_nvc[e] = cls;
        }
    }
}

// ---------------- kernel 3: exact top-K selection, 8 parallel phase-blocks --
__global__ void k_select2() {
    int b  = blockIdx.x >> 1;
    int ph = blockIdx.x & 1;           // 0 = positives, 1 = negatives
    int t = threadIdx.x;
    int lane = t & 31, wid = t >> 5;

    __shared__ int   scnt[NBINS];
    __shared__ float sred[256];
    __shared__ int   swsum[8];
    __shared__ int   sint[4];
    __shared__ unsigned long long skey[CAPB];
    __shared__ float sv1[CAPB], sv2[CAPB];

    const int*   cnt = (ph ? d_ncnt : d_pcnt) + b*NBINS;
    const float* s1  = (ph ? d_nsc  : d_psc ) + b*NBINS;
    const float* s2  = d_psr + b*NBINS;
    const unsigned long long* keyg = (ph ? d_nkey : d_pkey) + (size_t)b*NBINS*CAPB;
    const float* v1g = (ph ? d_nvc : d_pvc) + (size_t)b*NBINS*CAPB;
    const float* v2g = d_pvr + (size_t)b*NBINS*CAPB;

    int K;
    if (ph == 0) {
        K = NPOSMAX;
    } else {
        // negatives need num_pos = min(total positives, NPOSMAX)
        const int4* pv = (const int4*)(d_pcnt + b*NBINS);
        int s = 0;
        #pragma unroll
        for (int g = 0; g < 4; g++) { int4 c = pv[t*4 + g]; s += c.x + c.y + c.z + c.w; }
        #pragma unroll
        for (int off = 16; off; off >>= 1) s += __shfl_xor_sync(0xFFFFFFFFu, s, off);
        if (lane == 0) swsum[wid] = s;
        __syncthreads();
        if (t == 0) { int tot = 0; for (int w = 0; w < 8; w++) tot += swsum[w]; sint[3] = tot; }
        __syncthreads();
        int np = sint[3]; if (np > NPOSMAX) np = NPOSMAX;
        K = NPI - np;
        __syncthreads();
    }

    // thread t owns 16 bins [base, base+16), base descending with t
    int base = NBINS - 16*(t+1);
    int cs = 0;
    {
        const int4* cv = (const int4*)(cnt + base);
        #pragma unroll
        for (int g = 0; g < 4; g++) {
            int4 c = cv[g];
            scnt[t*16 + g*4 + 0] = c.x; scnt[t*16 + g*4 + 1] = c.y;
            scnt[t*16 + g*4 + 2] = c.z; scnt[t*16 + g*4 + 3] = c.w;
            cs += c.x + c.y + c.z + c.w;
        }
    }

    // warp-shuffle inclusive scan over thread order (t ascending = bins descending)
    int v = cs;
    #pragma unroll
    for (int off = 1; off < 32; off <<= 1) {
        int n = __shfl_up_sync(0xFFFFFFFFu, v, off);
        if (lane >= off) v += n;
    }
    if (lane == 31) swsum[wid] = v;
    __syncthreads();
    if (t < 8) {
        int x = swsum[t];
        #pragma unroll
        for (int off = 1; off < 8; off <<= 1) {
            int n = __shfl_up_sync(0x000000FFu, x, off);
            if (t >= off) x += n;
        }
        swsum[t] = x;
    }
    __syncthreads();
    int incl  = v + (wid ? swsum[wid-1] : 0);
    int excl  = incl - cs;
    int total = swsum[7];

    if (t == 0) { sint[0] = -1; sint[1] = 0; }
    __syncthreads();
    if (total > K && excl < K && incl >= K) {     // exactly one thread
        int cum = excl;
        #pragma unroll
        for (int k = 15; k >= 0; k--) {           // descending bin order
            int cc = scnt[t*16 + k];
            if (cum + cc >= K) { sint[0] = base + k; sint[1] = K - cum; break; }
            cum += cc;
        }
    }
    __syncthreads();
    int binT = sint[0], Kp = sint[1];

    // whole-bin sums for bins strictly above the threshold bin
    float a1 = 0.f, a2 = 0.f;
    {
        const float4* s1v = (const float4*)(s1 + base);
        #pragma unroll
        for (int g = 0; g < 4; g++) {
            float4 x = s1v[g];
            if (base + g*4 + 0 > binT) a1 += x.x;
            if (base + g*4 + 1 > binT) a1 += x.y;
            if (base + g*4 + 2 > binT) a1 += x.z;
            if (base + g*4 + 3 > binT) a1 += x.w;
        }
        if (ph == 0) {
            const float4* s2v = (const float4*)(s2 + base);
            #pragma unroll
            for (int g = 0; g < 4; g++) {
                float4 x = s2v[g];
                if (base + g*4 + 0 > binT) a2 += x.x;
                if (base + g*4 + 1 > binT) a2 += x.y;
                if (base + g*4 + 2 > binT) a2 += x.z;
                if (base + g*4 + 3 > binT) a2 += x.w;
            }
        }
    }

    // boundary bin: exact rank selection on unique keys
    if (binT >= 0) {
        int nt = cnt[binT]; if (nt > CAPB) nt = CAPB;
        size_t bb2 = (size_t)binT * CAPB;
        for (int e = t; e < nt; e += 256) {
            skey[e] = keyg[bb2 + e];
            sv1[e]  = v1g[bb2 + e];
            if (ph == 0) sv2[e] = v2g[bb2 + e];
        }
        __syncthreads();
        for (int e = t; e < nt; e += 256) {
            unsigned long long ke = skey[e];
            int rank = 0;
            for (int q = 0; q < nt; q++) rank += (skey[q] > ke);
            if (rank < Kp) { a1 += sv1[e]; if (ph == 0) a2 += sv2[e]; }
        }
    }
    __syncthreads();

    sred[t] = a1; __syncthreads();
    #pragma unroll
    for (int off = 128; off; off >>= 1) { if (t < off) sred[t] += sred[t + off]; __syncthreads(); }
    float r1 = sred[0];
    __syncthreads();
    sred[t] = a2; __syncthreads();
    #pragma unroll
    for (int off = 128; off; off >>= 1) { if (t < off) sred[t] += sred[t + off]; __syncthreads(); }
    float r2 = sred[0];

    if (t == 0) {
        d_ocls[blockIdx.x] = r1;
        d_oreg[blockIdx.x] = (ph == 0) ? r2 : 0.f;
        d_ocnt[blockIdx.x] = (total < K) ? total : K;
    }
}

// ---------------- kernel 4: combine and normalize ---------------------------
__global__ void k_final(float* __restrict__ out) {
    float cs = 0.f, rs = 0.f; int cn = 0;
    #pragma unroll
    for (int i = 0; i < 2*BB; i++) { cs += d_ocls[i]; rs += d_oreg[i]; cn += d_ocnt[i]; }
    float tot = (float)cn;
    out[0] = cs / tot;
    out[1] = rs / tot;
}

// ---------------- launch ----------------------------------------------------
extern "C" void kernel_launch(void* const* d_in, const int* in_sizes, int n_in,
                              void* d_out, int out_size) {
    const float* anchors = (const float*)d_in[0];
    const float* logits  = (const float*)d_in[1];
    const float* bregs   = (const float*)d_in[2];
    const float* sizes   = (const float*)d_in[3];
    const float* targets = (const float*)d_in[4];
    float* out = (float*)d_out;

    k_init<<<(BB*NBINS + 255)/256, 256>>>();
    k_colmax<<<BB*(NN/256), 256>>>(anchors, targets);
    k_classify<<<BB*(NN/256), 256>>>(anchors, logits, bregs, sizes, targets);
    k_select2<<<2*BB, 256>>>();
    k_final<<<1, 1>>>(out);
}